// round 1
// baseline (speedup 1.0000x reference)
#include <cuda_runtime.h>
#include <math.h>

#define NTOK 8192
#define DDIM 1024
#define HDIM 4096
#define NEXP 8
#define CAP  2048
#define NENT (2*NTOK)

// ---------------- scratch (device globals; no allocation allowed) ----------------
__device__ float g_disp[(size_t)NEXP*CAP*DDIM];          // 64 MB
__device__ float g_h[(size_t)NEXP*CAP*HDIM];             // 256 MB
__device__ float g_y[(size_t)NEXP*CAP*DDIM];             // 64 MB
__device__ int   g_eid[NENT];
__device__ float g_gv[NENT];
__device__ int   g_pos[NENT];

// ---------------- gate: logits, softmax top-2, normalized gates ----------------
__global__ void gate_kernel(const float* __restrict__ x, const float* __restrict__ wg) {
    __shared__ float wsh[NEXP*DDIM];   // transposed: wsh[e*DDIM + d]
    int tid = threadIdx.x;
    for (int i = tid; i < NEXP*DDIM; i += 256) {
        int d = i / NEXP, e = i % NEXP;
        wsh[e*DDIM + d] = wg[i];
    }
    __syncthreads();

    int warp = tid >> 5, lane = tid & 31;
    int n = blockIdx.x * 8 + warp;
    const float* xr = x + (size_t)n * DDIM;

    float acc[NEXP];
#pragma unroll
    for (int e = 0; e < NEXP; e++) acc[e] = 0.f;
    for (int d = lane; d < DDIM; d += 32) {
        float xv = xr[d];
#pragma unroll
        for (int e = 0; e < NEXP; e++) acc[e] += xv * wsh[e*DDIM + d];
    }
#pragma unroll
    for (int e = 0; e < NEXP; e++) {
#pragma unroll
        for (int off = 16; off; off >>= 1)
            acc[e] += __shfl_xor_sync(0xffffffffu, acc[e], off);
    }
    if (lane == 0) {
        float l0 = -1e30f; int i0 = 0;
#pragma unroll
        for (int e = 0; e < NEXP; e++) if (acc[e] > l0) { l0 = acc[e]; i0 = e; }
        float l1 = -1e30f; int i1 = 0;
#pragma unroll
        for (int e = 0; e < NEXP; e++) if (e != i0 && acc[e] > l1) { l1 = acc[e]; i1 = e; }
        // softmax Z cancels in top-2 renormalization: g0 = e^{l0}/(e^{l0}+e^{l1})
        float r  = expf(l1 - l0);
        float g0 = 1.f / (1.f + r);
        g_eid[n]        = i0;
        g_eid[NTOK + n] = i1;
        g_gv[n]         = g0;
        g_gv[NTOK + n]  = 1.f - g0;
    }
}

// ---------------- GShard capacity positions (single CTA scan) ----------------
// Entry order: all k=0 choices (token 0..N-1), then all k=1 choices. Exactly matches
// the reference's per-k cumsum with cross-k offset.
__global__ void pos_kernel() {
    __shared__ int cnt[1024][NEXP];
    int t = threadIdx.x;
    int base = t * 16;
#pragma unroll
    for (int e = 0; e < NEXP; e++) cnt[t][e] = 0;
    for (int j = 0; j < 16; j++) cnt[t][g_eid[base + j]]++;
    __syncthreads();

    if (t < 256) {           // warps 0..7: warp w scans expert w over 1024 chunks
        int w = t >> 5, lane = t & 31;
        int s = 0;
        for (int j = 0; j < 32; j++) s += cnt[lane*32 + j][w];
        int incl = s;
#pragma unroll
        for (int off = 1; off < 32; off <<= 1) {
            int v = __shfl_up_sync(0xffffffffu, incl, off);
            if (lane >= off) incl += v;
        }
        int run = incl - s;  // exclusive prefix for this lane's 32 chunks
        for (int j = 0; j < 32; j++) {
            int v = cnt[lane*32 + j][w];
            cnt[lane*32 + j][w] = run;
            run += v;
        }
    }
    __syncthreads();

    for (int j = 0; j < 16; j++) {
        int i = base + j;
        int e = g_eid[i];
        int p = cnt[t][e]++;
        if (p < CAP) {
            g_pos[i] = p;
        } else {
            g_pos[i] = -1;
            g_gv[i]  = 0.f;     // dropped token: gate zeroed (post-normalization)
        }
    }
}

// ---------------- dispatch scatter ----------------
__global__ void dispatch_kernel(const float* __restrict__ x) {
    int i = blockIdx.x;
    int p = g_pos[i];
    if (p < 0) return;
    int e = g_eid[i];
    int n = i & (NTOK - 1);
    const float4* src = (const float4*)(x + (size_t)n * DDIM);
    float4* dst = (float4*)(g_disp + (size_t)(e*CAP + p) * DDIM);
    dst[threadIdx.x] = src[threadIdx.x];
}

// ---------------- tf32 GEMM (mma.sync.m16n8k8) ----------------
__device__ __forceinline__ unsigned f2tf(float f) {
    unsigned r;
    asm("cvt.rna.tf32.f32 %0, %1;" : "=r"(r) : "f"(f));
    return r;
}

__device__ __forceinline__ void mma_tf32(float* d, const unsigned* a, const unsigned* b) {
    asm volatile(
        "mma.sync.aligned.m16n8k8.row.col.f32.tf32.tf32.f32 "
        "{%0,%1,%2,%3}, {%4,%5,%6,%7}, {%8,%9}, {%0,%1,%2,%3};\n"
        : "+f"(d[0]), "+f"(d[1]), "+f"(d[2]), "+f"(d[3])
        : "r"(a[0]), "r"(a[1]), "r"(a[2]), "r"(a[3]), "r"(b[0]), "r"(b[1]));
}

__device__ __forceinline__ float gelu_exact(float v) {
    return 0.5f * v * (1.f + erff(v * 0.70710678118654752f));
}

// CTA tile 128x128, BK=16, 256 threads (8 warps as 4m x 2n, warp tile 32x64)
template<int KD, int ND, bool DO_GELU>
__device__ __forceinline__ void gemm_body(const float* __restrict__ A,
                                          const float* __restrict__ B,
                                          const float* __restrict__ bias,
                                          float* __restrict__ C) {
    __shared__ unsigned As[16][132];
    __shared__ unsigned Bs[16][132];

    int tid  = threadIdx.x;
    int lane = tid & 31, warp = tid >> 5;
    int wm = (warp >> 1) * 32;
    int wn = (warp & 1) * 64;
    int tig = lane & 3, grp = lane >> 2;
    int bm = blockIdx.y * 128, bn = blockIdx.x * 128;

    float acc[2][8][4];
#pragma unroll
    for (int mi = 0; mi < 2; mi++)
#pragma unroll
        for (int ni = 0; ni < 8; ni++)
#pragma unroll
            for (int q = 0; q < 4; q++) acc[mi][ni][q] = 0.f;

    for (int kt = 0; kt < KD; kt += 16) {
        // load A tile [128 x 16] -> As[k][m]
#pragma unroll
        for (int i = 0; i < 2; i++) {
            int t = tid + i * 256;
            int row = t >> 2, cv = (t & 3) * 4;
            const float4 v = *(const float4*)(A + (size_t)(bm + row) * KD + kt + cv);
            As[cv + 0][row] = f2tf(v.x);
            As[cv + 1][row] = f2tf(v.y);
            As[cv + 2][row] = f2tf(v.z);
            As[cv + 3][row] = f2tf(v.w);
        }
        // load B tile [16 x 128] -> Bs[k][n]
#pragma unroll
        for (int i = 0; i < 2; i++) {
            int t = tid + i * 256;
            int kr = t >> 5, cv = (t & 31) * 4;
            const float4 v = *(const float4*)(B + (size_t)(kt + kr) * ND + bn + cv);
            uint4 u;
            u.x = f2tf(v.x); u.y = f2tf(v.y); u.z = f2tf(v.z); u.w = f2tf(v.w);
            *(uint4*)&Bs[kr][cv] = u;
        }
        __syncthreads();

#pragma unroll
        for (int ks = 0; ks < 16; ks += 8) {
            unsigned a[2][4], b[8][2];
#pragma unroll
            for (int mi = 0; mi < 2; mi++) {
                int m0 = wm + mi * 16;
                a[mi][0] = As[ks + tig][m0 + grp];
                a[mi][1] = As[ks + tig][m0 + grp + 8];
                a[mi][2] = As[ks + tig + 4][m0 + grp];
                a[mi][3] = As[ks + tig + 4][m0 + grp + 8];
            }
#pragma unroll
            for (int ni = 0; ni < 8; ni++) {
                int n0 = wn + ni * 8;
                b[ni][0] = Bs[ks + tig][n0 + grp];
                b[ni][1] = Bs[ks + tig + 4][n0 + grp];
            }
#pragma unroll
            for (int mi = 0; mi < 2; mi++)
#pragma unroll
                for (int ni = 0; ni < 8; ni++)
                    mma_tf32(acc[mi][ni], a[mi], b[ni]);
        }
        __syncthreads();
    }

    // epilogue
#pragma unroll
    for (int mi = 0; mi < 2; mi++) {
#pragma unroll
        for (int ni = 0; ni < 8; ni++) {
            int row = bm + wm + mi * 16 + grp;
            int col = bn + wn + ni * 8 + tig * 2;
            float b0 = bias[col], b1v = bias[col + 1];
            float v0 = acc[mi][ni][0] + b0;
            float v1 = acc[mi][ni][1] + b1v;
            float v2 = acc[mi][ni][2] + b0;
            float v3 = acc[mi][ni][3] + b1v;
            if (DO_GELU) {
                v0 = gelu_exact(v0); v1 = gelu_exact(v1);
                v2 = gelu_exact(v2); v3 = gelu_exact(v3);
            }
            C[(size_t)row * ND + col]           = v0;
            C[(size_t)row * ND + col + 1]       = v1;
            C[(size_t)(row + 8) * ND + col]     = v2;
            C[(size_t)(row + 8) * ND + col + 1] = v3;
        }
    }
}

__global__ void __launch_bounds__(256, 2)
gemm1_kernel(const float* __restrict__ w1, const float* __restrict__ b1) {
    int e = blockIdx.z;
    gemm_body<DDIM, HDIM, true>(g_disp + (size_t)e*CAP*DDIM,
                                w1 + (size_t)e*DDIM*HDIM,
                                b1 + (size_t)e*HDIM,
                                g_h + (size_t)e*CAP*HDIM);
}

__global__ void __launch_bounds__(256, 2)
gemm2_kernel(const float* __restrict__ w2, const float* __restrict__ b2) {
    int e = blockIdx.z;
    gemm_body<HDIM, DDIM, false>(g_h + (size_t)e*CAP*HDIM,
                                 w2 + (size_t)e*HDIM*DDIM,
                                 b2 + (size_t)e*DDIM,
                                 g_y + (size_t)e*CAP*DDIM);
}

// ---------------- combine (gather + gate-weighted sum) ----------------
__global__ void combine_kernel(float* __restrict__ out) {
    int n = blockIdx.x;
    int t = threadIdx.x;
    float4 acc = make_float4(0.f, 0.f, 0.f, 0.f);
#pragma unroll
    for (int kk = 0; kk < 2; kk++) {
        int i = kk * NTOK + n;
        int p = g_pos[i];
        if (p >= 0) {
            float g = g_gv[i];
            const float4 v = *((const float4*)(g_y + (size_t)(g_eid[i]*CAP + p) * DDIM) + t);
            acc.x += g * v.x; acc.y += g * v.y;
            acc.z += g * v.z; acc.w += g * v.w;
        }
    }
    ((float4*)out)[(size_t)n * 256 + t] = acc;
}

// ---------------- launch ----------------
extern "C" void kernel_launch(void* const* d_in, const int* in_sizes, int n_in,
                              void* d_out, int out_size) {
    const float* x  = (const float*)d_in[0];
    const float* wg = (const float*)d_in[1];
    const float* w1 = (const float*)d_in[2];
    const float* b1 = (const float*)d_in[3];
    const float* w2 = (const float*)d_in[4];
    const float* b2 = (const float*)d_in[5];
    float* out = (float*)d_out;

    gate_kernel<<<NTOK/8, 256>>>(x, wg);
    pos_kernel<<<1, 1024>>>();
    dispatch_kernel<<<NENT, 256>>>(x);
    gemm1_kernel<<<dim3(HDIM/128, CAP/128, NEXP), 256>>>(w1, b1);
    gemm2_kernel<<<dim3(DDIM/128, CAP/128, NEXP), 256>>>(w2, b2);
    combine_kernel<<<NTOK, 256>>>(out);
}

// round 3
// speedup vs baseline: 3.4150x; 3.4150x over previous
#include <cuda_runtime.h>
#include <cuda_fp16.h>
#include <math.h>
#include <stdint.h>

#define NTOK 8192
#define DDIM 1024
#define HDIM 4096
#define NEXP 8
#define CAP  2048
#define NENT (2*NTOK)

#define STAGES 3
#define STAGE_BYTES 32768          // A 16KB + B 16KB (128 rows x 128B, fp16 BK=64)
#define DSMEM_BYTES (STAGES*STAGE_BYTES + 1024)

// ---------------- scratch (device globals; no allocation allowed) ----------------
__device__ __half g_disp[(size_t)NEXP*CAP*DDIM];   // 32 MB
__device__ __half g_h[(size_t)NEXP*CAP*HDIM];      // 128 MB
__device__ float  g_y[(size_t)NEXP*CAP*DDIM];      // 64 MB
__device__ __half g_w1t[(size_t)NEXP*DDIM*HDIM];   // 64 MB  [e][h][d]
__device__ __half g_w2t[(size_t)NEXP*HDIM*DDIM];   // 64 MB  [e][d][h]
__device__ int    g_eid[NENT];
__device__ float  g_gv[NENT];
__device__ int    g_pos[NENT];

// ---------------- helpers ----------------
__device__ __forceinline__ uint32_t s2u(const void* p) {
    uint32_t a;
    asm("{ .reg .u64 t; cvta.to.shared.u64 t, %1; cvt.u32.u64 %0, t; }" : "=r"(a) : "l"(p));
    return a;
}
__device__ __forceinline__ void cpasync16(uint32_t dst, const void* src) {
    asm volatile("cp.async.cg.shared.global [%0], [%1], 16;" :: "r"(dst), "l"(src));
}
__device__ __forceinline__ void cp_commit() { asm volatile("cp.async.commit_group;" ::: "memory"); }
template<int N> __device__ __forceinline__ void cp_wait() {
    asm volatile("cp.async.wait_group %0;" :: "n"(N) : "memory");
}
__device__ __forceinline__ void ldsm4(uint32_t* d, uint32_t addr) {
    asm volatile("ldmatrix.sync.aligned.m8n8.x4.shared.b16 {%0,%1,%2,%3}, [%4];"
        : "=r"(d[0]), "=r"(d[1]), "=r"(d[2]), "=r"(d[3]) : "r"(addr));
}
__device__ __forceinline__ void mma16816(float* d, const uint32_t* a, const uint32_t* b) {
    asm volatile(
        "mma.sync.aligned.m16n8k16.row.col.f32.f16.f16.f32 "
        "{%0,%1,%2,%3}, {%4,%5,%6,%7}, {%8,%9}, {%0,%1,%2,%3};"
        : "+f"(d[0]), "+f"(d[1]), "+f"(d[2]), "+f"(d[3])
        : "r"(a[0]), "r"(a[1]), "r"(a[2]), "r"(a[3]), "r"(b[0]), "r"(b[1]));
}
__device__ __forceinline__ float gelu_exact(float v) {
    return 0.5f * v * (1.f + erff(v * 0.70710678118654752f));
}

// ---------------- gate ----------------
__global__ void gate_kernel(const float* __restrict__ x, const float* __restrict__ wg) {
    __shared__ float wsh[NEXP*DDIM];
    int tid = threadIdx.x;
    for (int i = tid; i < NEXP*DDIM; i += 256) {
        int d = i / NEXP, e = i % NEXP;
        wsh[e*DDIM + d] = wg[i];
    }
    __syncthreads();
    int warp = tid >> 5, lane = tid & 31;
    int n = blockIdx.x * 8 + warp;
    const float* xr = x + (size_t)n * DDIM;
    float acc[NEXP];
#pragma unroll
    for (int e = 0; e < NEXP; e++) acc[e] = 0.f;
    for (int d = lane; d < DDIM; d += 32) {
        float xv = xr[d];
#pragma unroll
        for (int e = 0; e < NEXP; e++) acc[e] += xv * wsh[e*DDIM + d];
    }
#pragma unroll
    for (int e = 0; e < NEXP; e++) {
#pragma unroll
        for (int off = 16; off; off >>= 1)
            acc[e] += __shfl_xor_sync(0xffffffffu, acc[e], off);
    }
    if (lane == 0) {
        float l0 = -1e30f; int i0 = 0;
#pragma unroll
        for (int e = 0; e < NEXP; e++) if (acc[e] > l0) { l0 = acc[e]; i0 = e; }
        float l1 = -1e30f; int i1 = 0;
#pragma unroll
        for (int e = 0; e < NEXP; e++) if (e != i0 && acc[e] > l1) { l1 = acc[e]; i1 = e; }
        float r  = expf(l1 - l0);
        float g0 = 1.f / (1.f + r);
        g_eid[n]        = i0;
        g_eid[NTOK + n] = i1;
        g_gv[n]         = g0;
        g_gv[NTOK + n]  = 1.f - g0;
    }
}

// ---------------- GShard capacity positions ----------------
__global__ void pos_kernel() {
    __shared__ int cnt[1024][NEXP];
    int t = threadIdx.x;
    int base = t * 16;
#pragma unroll
    for (int e = 0; e < NEXP; e++) cnt[t][e] = 0;
    for (int j = 0; j < 16; j++) cnt[t][g_eid[base + j]]++;
    __syncthreads();
    if (t < 256) {
        int w = t >> 5, lane = t & 31;
        int s = 0;
        for (int j = 0; j < 32; j++) s += cnt[lane*32 + j][w];
        int incl = s;
#pragma unroll
        for (int off = 1; off < 32; off <<= 1) {
            int v = __shfl_up_sync(0xffffffffu, incl, off);
            if (lane >= off) incl += v;
        }
        int run = incl - s;
        for (int j = 0; j < 32; j++) {
            int v = cnt[lane*32 + j][w];
            cnt[lane*32 + j][w] = run;
            run += v;
        }
    }
    __syncthreads();
    for (int j = 0; j < 16; j++) {
        int i = base + j;
        int e = g_eid[i];
        int p = cnt[t][e]++;
        if (p < CAP) {
            g_pos[i] = p;
        } else {
            g_pos[i] = -1;
            g_gv[i]  = 0.f;
        }
    }
}

// ---------------- dispatch scatter (f32 -> fp16) ----------------
__global__ void dispatch_kernel(const float* __restrict__ x) {
    int i = blockIdx.x;
    int p = g_pos[i];
    if (p < 0) return;
    int e = g_eid[i];
    int n = i & (NTOK - 1);
    const float4 v = ((const float4*)(x + (size_t)n * DDIM))[threadIdx.x];
    __half2* dst = (__half2*)(g_disp + (size_t)(e*CAP + p) * DDIM) + threadIdx.x * 2;
    dst[0] = __floats2half2_rn(v.x, v.y);
    dst[1] = __floats2half2_rn(v.z, v.w);
}

// ---------------- weight transpose + fp16 convert: W[e][KD][ND] -> Wt[e][ND][KD] ----------------
__global__ void transpose_kernel(const float* __restrict__ W, __half* __restrict__ Wt,
                                 int KD, int ND) {
    __shared__ float t[32][33];
    int e = blockIdx.z;
    const float* Wp = W  + (size_t)e * KD * ND;
    __half*      Wo = Wt + (size_t)e * KD * ND;
    int n0 = blockIdx.x * 32, k0 = blockIdx.y * 32;
    int tx = threadIdx.x, ty = threadIdx.y;
#pragma unroll
    for (int j = 0; j < 32; j += 8)
        t[ty + j][tx] = Wp[(size_t)(k0 + ty + j) * ND + n0 + tx];
    __syncthreads();
#pragma unroll
    for (int j = 0; j < 32; j += 8)
        Wo[(size_t)(n0 + ty + j) * KD + k0 + tx] = __float2half_rn(t[tx][ty + j]);
}

// ---------------- fp16 mma GEMM: C[m,n] = sum_k A[m,k]*Bt[n,k] (+bias, opt GELU) ----------------
// CTA 128x128, BK=64 (128B SW128 rows), 3-stage cp.async, 8 warps (4m x 2n, warp 32x64)
template<int KDIM, int NDIM, bool DO_GELU, typename OutT>
__global__ void __launch_bounds__(256, 2)
gemm_mma(const __half* __restrict__ Abase, const __half* __restrict__ Btbase,
         const float* __restrict__ biasb, OutT* __restrict__ Cbase) {
    extern __shared__ char dynsm[];
    uint32_t sbase = (s2u(dynsm) + 1023u) & ~1023u;

    int tid = threadIdx.x, lane = tid & 31, warp = tid >> 5;
    int e = blockIdx.z;
    int bm = blockIdx.y * 128, bn = blockIdx.x * 128;
    const __half* A  = Abase  + (size_t)e * CAP  * KDIM + (size_t)bm * KDIM;
    const __half* Bt = Btbase + (size_t)e * NDIM * KDIM + (size_t)bn * KDIM;
    const float* bias = biasb + (size_t)e * NDIM + bn;

    constexpr int KT = KDIM / 64;

    int wm = (warp >> 1) * 32;   // warp tile 32x64
    int wn = (warp & 1) * 64;
    int r8 = lane & 7, t4 = lane >> 3;

    float acc[2][8][4];
#pragma unroll
    for (int mi = 0; mi < 2; mi++)
#pragma unroll
        for (int ni = 0; ni < 8; ni++)
#pragma unroll
            for (int q = 0; q < 4; q++) acc[mi][ni][q] = 0.f;

    auto load_stage = [&](int kt) {
        uint32_t sa = sbase + (uint32_t)(kt % STAGES) * STAGE_BYTES;
        uint32_t sb = sa + 16384;
        const __half* Ap = A  + kt * 64;
        const __half* Bp = Bt + kt * 64;
#pragma unroll
        for (int i = 0; i < 4; i++) {
            int idx = i * 256 + tid;           // 1024 16B-chunks per operand
            int row = idx >> 3, c = idx & 7;
            uint32_t so = (uint32_t)((row * 8 + (c ^ (row & 7))) * 16);
            cpasync16(sa + so, Ap + (size_t)row * KDIM + c * 8);
            cpasync16(sb + so, Bp + (size_t)row * KDIM + c * 8);
        }
    };

    // prologue: stages 0..S-2
#pragma unroll
    for (int kt = 0; kt < STAGES - 1; kt++) { load_stage(kt); cp_commit(); }

    for (int kt = 0; kt < KT; kt++) {
        cp_wait<STAGES - 2>();
        __syncthreads();

        int ktp = kt + STAGES - 1;
        if (ktp < KT) load_stage(ktp);
        cp_commit();

        uint32_t sA = sbase + (uint32_t)(kt % STAGES) * STAGE_BYTES;
        uint32_t sB = sA + 16384;
#pragma unroll
        for (int ks4 = 0; ks4 < 4; ks4++) {
            int kc = ks4 * 2;
            uint32_t a[2][4], b[8][2];
#pragma unroll
            for (int mi = 0; mi < 2; mi++) {
                int row = wm + mi * 16 + (t4 & 1) * 8 + r8;
                int cc  = kc + (t4 >> 1);
                ldsm4(a[mi], sA + (uint32_t)(row * 128 + ((cc ^ (row & 7)) << 4)));
            }
#pragma unroll
            for (int nj = 0; nj < 4; nj++) {
                int row = wn + nj * 16 + (t4 >> 1) * 8 + r8;
                int cc  = kc + (t4 & 1);
                uint32_t q[4];
                ldsm4(q, sB + (uint32_t)(row * 128 + ((cc ^ (row & 7)) << 4)));
                b[2*nj][0]   = q[0]; b[2*nj][1]   = q[1];
                b[2*nj+1][0] = q[2]; b[2*nj+1][1] = q[3];
            }
#pragma unroll
            for (int mi = 0; mi < 2; mi++)
#pragma unroll
                for (int ni = 0; ni < 8; ni++)
                    mma16816(acc[mi][ni], a[mi], b[ni]);
        }
        __syncthreads();
    }

    // epilogue
    int grp = lane >> 2, tig = lane & 3;
    OutT* Ce = Cbase + (size_t)e * CAP * NDIM;
#pragma unroll
    for (int mi = 0; mi < 2; mi++) {
#pragma unroll
        for (int ni = 0; ni < 8; ni++) {
            int row = bm + wm + mi * 16 + grp;
            int col = bn + wn + ni * 8 + tig * 2;
            float b0 = bias[wn + ni * 8 + tig * 2];
            float b1v = bias[wn + ni * 8 + tig * 2 + 1];
            float v0 = acc[mi][ni][0] + b0;
            float v1 = acc[mi][ni][1] + b1v;
            float v2 = acc[mi][ni][2] + b0;
            float v3 = acc[mi][ni][3] + b1v;
            if (DO_GELU) {
                v0 = gelu_exact(v0); v1 = gelu_exact(v1);
                v2 = gelu_exact(v2); v3 = gelu_exact(v3);
            }
            if (sizeof(OutT) == 2) {
                *(__half2*)((__half*)Ce + (size_t)row * NDIM + col) = __floats2half2_rn(v0, v1);
                *(__half2*)((__half*)Ce + (size_t)(row + 8) * NDIM + col) = __floats2half2_rn(v2, v3);
            } else {
                *(float2*)((float*)Ce + (size_t)row * NDIM + col) = make_float2(v0, v1);
                *(float2*)((float*)Ce + (size_t)(row + 8) * NDIM + col) = make_float2(v2, v3);
            }
        }
    }
}

// bias is per-expert [E, N]; wrapper passes correct base
__global__ void combine_kernel(float* __restrict__ out) {
    int n = blockIdx.x;
    int t = threadIdx.x;
    float4 acc = make_float4(0.f, 0.f, 0.f, 0.f);
#pragma unroll
    for (int kk = 0; kk < 2; kk++) {
        int i = kk * NTOK + n;
        int p = g_pos[i];
        if (p >= 0) {
            float g = g_gv[i];
            const float4 v = *((const float4*)(g_y + (size_t)(g_eid[i]*CAP + p) * DDIM) + t);
            acc.x += g * v.x; acc.y += g * v.y;
            acc.z += g * v.z; acc.w += g * v.w;
        }
    }
    ((float4*)out)[(size_t)n * 256 + t] = acc;
}

// ---------------- launch ----------------
extern "C" void kernel_launch(void* const* d_in, const int* in_sizes, int n_in,
                              void* d_out, int out_size) {
    const float* x  = (const float*)d_in[0];
    const float* wg = (const float*)d_in[1];
    const float* w1 = (const float*)d_in[2];
    const float* b1 = (const float*)d_in[3];
    const float* w2 = (const float*)d_in[4];
    const float* b2 = (const float*)d_in[5];
    float* out = (float*)d_out;

    static int attr_done = 0;
    if (!attr_done) {
        cudaFuncSetAttribute(gemm_mma<DDIM, HDIM, true,  __half>,
                             cudaFuncAttributeMaxDynamicSharedMemorySize, DSMEM_BYTES);
        cudaFuncSetAttribute(gemm_mma<HDIM, DDIM, false, float>,
                             cudaFuncAttributeMaxDynamicSharedMemorySize, DSMEM_BYTES);
        attr_done = 1;
    }

    __half* w1t;  cudaGetSymbolAddress((void**)&w1t,  g_w1t);
    __half* w2t;  cudaGetSymbolAddress((void**)&w2t,  g_w2t);
    __half* disp; cudaGetSymbolAddress((void**)&disp, g_disp);
    __half* hbuf; cudaGetSymbolAddress((void**)&hbuf, g_h);
    float*  ybuf; cudaGetSymbolAddress((void**)&ybuf, g_y);

    gate_kernel<<<NTOK/8, 256>>>(x, wg);
    pos_kernel<<<1, 1024>>>();
    dispatch_kernel<<<NENT, 256>>>(x);
    transpose_kernel<<<dim3(HDIM/32, DDIM/32, NEXP), dim3(32, 8)>>>(w1, w1t, DDIM, HDIM);
    transpose_kernel<<<dim3(DDIM/32, HDIM/32, NEXP), dim3(32, 8)>>>(w2, w2t, HDIM, DDIM);
    gemm_mma<DDIM, HDIM, true,  __half><<<dim3(HDIM/128, CAP/128, NEXP), 256, DSMEM_BYTES>>>(
        disp, w1t, b1, hbuf);
    gemm_mma<HDIM, DDIM, false, float><<<dim3(DDIM/128, CAP/128, NEXP), 256, DSMEM_BYTES>>>(
        hbuf, w2t, b2, ybuf);
    combine_kernel<<<NTOK, 256>>>(out);
}